// round 2
// baseline (speedup 1.0000x reference)
#include <cuda_runtime.h>
#include <cuda_bf16.h>

#define MM 9
#define DD 128
#define NT 32          // examples per block
#define THREADS 256    // 8 warps -> 2 per SMSP

// shared memory layout (floats)
#define SW_OFF   0                    // W[m]: 128 x 128 (xor-swizzled), 16384
#define SF_OFF   16384                // f tile: 32 x 128 = 4096 (reused as fsum)
#define SG_OFF   20480                // g: 32 x 9 x 128 = 36864
#define SMEM_FLOATS 57344
#define SMEM_BYTES (SMEM_FLOATS * 4)  // 229376 B (< 227 KB limit 232448)

__device__ __forceinline__ constexpr int pidx(int j, int k) {
    return j * 8 - j * (j - 1) / 2 + (k - j - 1);
}

__global__ void __launch_bounds__(THREADS, 1)
inter_rm_fused(const float* __restrict__ F,   // [N, 9, 128]
               const float* __restrict__ Wg,  // [9, 128, 128]
               float* __restrict__ out,       // [N, 128]
               int N)
{
    extern __shared__ float sm[];
    float4* sW4 = reinterpret_cast<float4*>(sm + SW_OFF);
    float4* sF4 = reinterpret_cast<float4*>(sm + SF_OFF);
    float*  sG  = sm + SG_OFF;
    const float4* Fg4 = reinterpret_cast<const float4*>(F);
    const float4* Wg4 = reinterpret_cast<const float4*>(Wg);

    const int tid  = threadIdx.x;
    const int lane = tid & 31;
    const int warp = tid >> 5;     // 0..7
    const int eg   = lane;         // e-lane: e = eg, eg+32, eg+64, eg+96
    const int nb   = warp * 4;     // 4 n-rows per warp
    const int n0   = blockIdx.x * NT;

    // fsum accumulated in registers of the loader threads (4 float4 slots each)
    float4 fsum[4];
    #pragma unroll
    for (int r = 0; r < 4; ++r) fsum[r] = make_float4(0.f, 0.f, 0.f, 0.f);

    // ---------------- Phase 1: g[m] = relu(f[:,m,:] @ W[m]^T) -----------------
    for (int m = 0; m < MM; ++m) {
        __syncthreads();   // previous-m reads done before overwriting sW/sF

        // load W[m] (128x128 fp32) into smem with xor swizzle (no padding)
        #pragma unroll
        for (int r = 0; r < 16; ++r) {
            int s = tid + r * THREADS;          // 0..4095 float4 slots
            int e = s >> 5, q = s & 31;
            sW4[e * 32 + (q ^ (e & 31))] = Wg4[m * 4096 + s];
        }
        // load f tile for slot m; accumulate fsum in regs
        #pragma unroll
        for (int r = 0; r < 4; ++r) {
            int s = tid + r * THREADS;          // 0..1023
            int i = s >> 5, q = s & 31;
            int n = n0 + i;
            float4 v = make_float4(0.f, 0.f, 0.f, 0.f);
            if (n < N) v = Fg4[(n * MM + m) * 32 + q];
            sF4[s] = v;
            fsum[r].x += v.x; fsum[r].y += v.y;
            fsum[r].z += v.z; fsum[r].w += v.w;
        }
        __syncthreads();

        float acc[4][4];
        #pragma unroll
        for (int i = 0; i < 4; ++i)
            #pragma unroll
            for (int c = 0; c < 4; ++c) acc[i][c] = 0.f;

        #pragma unroll 4
        for (int kk = 0; kk < 32; ++kk) {
            float4 w0 = sW4[(eg     ) * 32 + (kk ^ eg)];
            float4 w1 = sW4[(eg + 32) * 32 + (kk ^ eg)];
            float4 w2 = sW4[(eg + 64) * 32 + (kk ^ eg)];
            float4 w3 = sW4[(eg + 96) * 32 + (kk ^ eg)];
            #pragma unroll
            for (int i = 0; i < 4; ++i) {
                float4 fv = sF4[(nb + i) * 32 + kk];   // warp-uniform broadcast
                acc[i][0] = fmaf(fv.x, w0.x, acc[i][0]);
                acc[i][0] = fmaf(fv.y, w0.y, acc[i][0]);
                acc[i][0] = fmaf(fv.z, w0.z, acc[i][0]);
                acc[i][0] = fmaf(fv.w, w0.w, acc[i][0]);
                acc[i][1] = fmaf(fv.x, w1.x, acc[i][1]);
                acc[i][1] = fmaf(fv.y, w1.y, acc[i][1]);
                acc[i][1] = fmaf(fv.z, w1.z, acc[i][1]);
                acc[i][1] = fmaf(fv.w, w1.w, acc[i][1]);
                acc[i][2] = fmaf(fv.x, w2.x, acc[i][2]);
                acc[i][2] = fmaf(fv.y, w2.y, acc[i][2]);
                acc[i][2] = fmaf(fv.z, w2.z, acc[i][2]);
                acc[i][2] = fmaf(fv.w, w2.w, acc[i][2]);
                acc[i][3] = fmaf(fv.x, w3.x, acc[i][3]);
                acc[i][3] = fmaf(fv.y, w3.y, acc[i][3]);
                acc[i][3] = fmaf(fv.z, w3.z, acc[i][3]);
                acc[i][3] = fmaf(fv.w, w3.w, acc[i][3]);
            }
        }
        // relu + stash g in smem
        #pragma unroll
        for (int i = 0; i < 4; ++i) {
            float* gr = sG + ((nb + i) * MM + m) * DD;
            gr[eg     ] = fmaxf(acc[i][0], 0.f);
            gr[eg + 32] = fmaxf(acc[i][1], 0.f);
            gr[eg + 64] = fmaxf(acc[i][2], 0.f);
            gr[eg + 96] = fmaxf(acc[i][3], 0.f);
        }
    }
    __syncthreads();

    // spill fsum registers into the (dead) f-tile region
    #pragma unroll
    for (int r = 0; r < 4; ++r) sF4[tid + r * THREADS] = fsum[r];
    __syncthreads();

    // ---------------- Phase 2: edges colsum + output --------------------------
    const float4* sG4 = reinterpret_cast<const float4*>(sG);
    float4* out4 = reinterpret_cast<float4*>(out);

    #pragma unroll
    for (int ii = 0; ii < 4; ++ii) {
        const int i = warp * 4 + ii;
        const int n = n0 + i;

        float4 gm[MM];
        #pragma unroll
        for (int m = 0; m < MM; ++m)
            gm[m] = sG4[(i * MM + m) * 32 + lane];

        // per-lane partial squared distances over this lane's 4 dims
        float sp[36];
        #pragma unroll
        for (int j = 0; j < MM; ++j) {
            #pragma unroll
            for (int k = j + 1; k < MM; ++k) {
                float dx = gm[j].x - gm[k].x;
                float dy = gm[j].y - gm[k].y;
                float dz = gm[j].z - gm[k].z;
                float dw = gm[j].w - gm[k].w;
                float s  = dx * dx;
                s = fmaf(dy, dy, s);
                s = fmaf(dz, dz, s);
                s = fmaf(dw, dw, s);
                sp[pidx(j, k)] = s;
            }
        }

        // butterfly-reduce each pair; pair p parked on lane (p mod 32), slot A/B
        float mysA = 1.f, mysB = 1.f;
        #pragma unroll
        for (int p = 0; p < 36; ++p) {
            float v = sp[p];
            v += __shfl_xor_sync(0xffffffffu, v, 16);
            v += __shfl_xor_sync(0xffffffffu, v, 8);
            v += __shfl_xor_sync(0xffffffffu, v, 4);
            v += __shfl_xor_sync(0xffffffffu, v, 2);
            v += __shfl_xor_sync(0xffffffffu, v, 1);
            if (p < 32) { if (lane == p)      mysA = v; }
            else        { if (lane == p - 32) mysB = v; }
        }

        // edge = tanh(sqrt(s)) (0 when s<=0), via 1 - 2/(exp(2x)+1)
        float xA = (mysA > 0.f) ? mysA * __frsqrt_rn(mysA) : 0.f;
        float xB = (mysB > 0.f) ? mysB * __frsqrt_rn(mysB) : 0.f;
        float eA = 1.f - __fdividef(2.f, __expf(2.f * xA) + 1.f);
        float eB = 1.f - __fdividef(2.f, __expf(2.f * xB) + 1.f);

        // column sums cs[k] = sum_j edges[j][k], gathered via shfl
        float cs[MM];
        #pragma unroll
        for (int k = 0; k < MM; ++k) {
            float a = 0.f;
            #pragma unroll
            for (int j = 0; j < MM; ++j) {
                if (j == k) continue;
                const int p = (j < k) ? pidx(j, k) : pidx(k, j);
                float e = (p < 32) ? __shfl_sync(0xffffffffu, eA, p)
                                   : __shfl_sync(0xffffffffu, eB, p - 32);
                a += e;
            }
            cs[k] = a;
        }

        // y = 0.5 * (fsum + sum_k cs[k] * g[k])
        float4 fs = sF4[i * 32 + lane];
        float ux = 0.f, uy = 0.f, uz = 0.f, uw = 0.f;
        #pragma unroll
        for (int k = 0; k < MM; ++k) {
            ux = fmaf(cs[k], gm[k].x, ux);
            uy = fmaf(cs[k], gm[k].y, uy);
            uz = fmaf(cs[k], gm[k].z, uz);
            uw = fmaf(cs[k], gm[k].w, uw);
        }
        if (n < N) {
            float4 o;
            o.x = 0.5f * (fs.x + ux);
            o.y = 0.5f * (fs.y + uy);
            o.z = 0.5f * (fs.z + uz);
            o.w = 0.5f * (fs.w + uw);
            out4[n * 32 + lane] = o;
        }
    }
}

extern "C" void kernel_launch(void* const* d_in, const int* in_sizes, int n_in,
                              void* d_out, int out_size) {
    const float* F = (const float*)d_in[0];   // f [N,9,128] fp32
    const float* W = (const float*)d_in[1];   // W [9,128,128] fp32
    float* out = (float*)d_out;               // y [N,128] fp32
    const int N = in_sizes[0] / (MM * DD);

    cudaFuncSetAttribute(inter_rm_fused,
                         cudaFuncAttributeMaxDynamicSharedMemorySize, SMEM_BYTES);
    const int grid = (N + NT - 1) / NT;
    inter_rm_fused<<<grid, THREADS, SMEM_BYTES>>>(F, W, out, N);
}

// round 4
// speedup vs baseline: 1.3902x; 1.3902x over previous
#include <cuda_runtime.h>
#include <cuda_bf16.h>
#include <cstdint>

#define MM 9
#define DD 128
#define NT 32
#define THREADS 256

// ---- shared memory byte offsets -------------------------------------------
#define SW_HI   0            // W hi: 128x128 bf16 swizzled   (32768)
#define SW_LO   32768        // W lo                          (32768)
#define SF_HI   65536        // f hi: 32x128 bf16             (8192)
#define SF_LO   73728        // f lo                          (8192)
#define SG_OFF  81920        // g: 32x9x128 fp32              (147456)
#define SMEM_BYTES 229376    // <= 232448 (227 KB)

// swizzled byte offset of (row, float4-slot q) for a [rows x 128] bf16 tile,
// rows are 256B = 16 chunks of 16B; chunk xor'd with row&7 within 8-chunk half
__device__ __forceinline__ uint32_t bswz(int row, int q) {
    int c = q >> 1;
    int cs = (c & 8) | ((c & 7) ^ (row & 7));
    return (uint32_t)(row * 256 + cs * 16 + (q & 1) * 8);
}
// ldmatrix address for (row, 16B-chunk)
__device__ __forceinline__ uint32_t lmaddr(uint32_t base, int row, int chunk) {
    int cs = (chunk & 8) | ((chunk & 7) ^ (row & 7));
    return base + (uint32_t)(row * 256 + cs * 16);
}

__device__ __forceinline__ uint32_t smem_u32(const void* p) {
    uint32_t a;
    asm("{ .reg .u64 t; cvta.to.shared.u64 t, %1; cvt.u32.u64 %0, t; }" : "=r"(a) : "l"(p));
    return a;
}

#define LDSM_X4(r0, r1, r2, r3, a) \
    asm volatile("ldmatrix.sync.aligned.m8n8.x4.shared.b16 {%0,%1,%2,%3}, [%4];" \
                 : "=r"(r0), "=r"(r1), "=r"(r2), "=r"(r3) : "r"(a))

#define HMMA(d0, d1, d2, d3, a0, a1, a2, a3, b0, b1) \
    asm volatile("mma.sync.aligned.m16n8k16.row.col.f32.bf16.bf16.f32 " \
                 "{%0,%1,%2,%3}, {%4,%5,%6,%7}, {%8,%9}, {%0,%1,%2,%3};" \
                 : "+f"(d0), "+f"(d1), "+f"(d2), "+f"(d3) \
                 : "r"(a0), "r"(a1), "r"(a2), "r"(a3), "r"(b0), "r"(b1))

// split one float4 into hi/lo bf16 quads and store 8B to each buffer
__device__ __forceinline__ void st_split(char* base, uint32_t off_hi, uint32_t off_lo,
                                         uint32_t a, float4 v) {
    __nv_bfloat16 hx = __float2bfloat16(v.x), hy = __float2bfloat16(v.y);
    __nv_bfloat16 hz = __float2bfloat16(v.z), hw = __float2bfloat16(v.w);
    __nv_bfloat16 lx = __float2bfloat16(v.x - __bfloat162float(hx));
    __nv_bfloat16 ly = __float2bfloat16(v.y - __bfloat162float(hy));
    __nv_bfloat16 lz = __float2bfloat16(v.z - __bfloat162float(hz));
    __nv_bfloat16 lw = __float2bfloat16(v.w - __bfloat162float(hw));
    uint2 h = make_uint2((uint32_t)__bfloat16_as_ushort(hx) | ((uint32_t)__bfloat16_as_ushort(hy) << 16),
                         (uint32_t)__bfloat16_as_ushort(hz) | ((uint32_t)__bfloat16_as_ushort(hw) << 16));
    uint2 l = make_uint2((uint32_t)__bfloat16_as_ushort(lx) | ((uint32_t)__bfloat16_as_ushort(ly) << 16),
                         (uint32_t)__bfloat16_as_ushort(lz) | ((uint32_t)__bfloat16_as_ushort(lw) << 16));
    *reinterpret_cast<uint2*>(base + off_hi + a) = h;
    *reinterpret_cast<uint2*>(base + off_lo + a) = l;
}

__device__ __forceinline__ constexpr int pidx(int j, int k) {
    return j * 8 - j * (j - 1) / 2 + (k - j - 1);
}

__global__ void __launch_bounds__(THREADS, 1)
inter_rm_mma(const float* __restrict__ F,   // [N, 9, 128]
             const float* __restrict__ Wg,  // [9, 128, 128]
             float* __restrict__ out,       // [N, 128]
             int N)
{
    extern __shared__ char smem[];
    const uint32_t sb = smem_u32(smem);
    float* sG = reinterpret_cast<float*>(smem + SG_OFF);
    const float4* Fg4 = reinterpret_cast<const float4*>(F);
    const float4* Wg4 = reinterpret_cast<const float4*>(Wg);

    const int tid  = threadIdx.x;
    const int lane = tid & 31;
    const int warp = tid >> 5;          // 0..7
    const int wr   = warp >> 2;         // warp row group: rows [16wr, 16wr+16)
    const int wc   = warp & 3;          // warp col group: cols [32wc, 32wc+32)
    const int n0   = blockIdx.x * NT;

    // fsum accumulators (4 float4 slots per thread across the f tile)
    float4 fsum[4];
    #pragma unroll
    for (int r = 0; r < 4; ++r) fsum[r] = make_float4(0.f, 0.f, 0.f, 0.f);

    // precomputed ldmatrix lane addresses (row/chunk patterns fixed per lane)
    const int a_row = 16 * wr + (lane & 15);
    const int a_ch  = lane >> 4;                 // 0/1 -> k-half
    const int b_rlo = (lane & 7) + ((lane >> 4) << 3);   // e row offset within 16
    const int b_ch  = (lane >> 3) & 1;                   // k-half chunk

    // ------------- Phase 1: g[m] = relu(f @ W_m^T) via split-bf16 HMMA --------
    for (int m = 0; m < MM; ++m) {
        __syncthreads();

        // convert W_m into split-bf16 smem
        #pragma unroll
        for (int it = 0; it < 16; ++it) {
            int s = tid + it * THREADS;         // 0..4095
            int row = s >> 5, q = s & 31;
            st_split(smem, SW_HI, SW_LO, bswz(row, q), Wg4[(size_t)m * 4096 + s]);
        }
        // convert f tile, accumulate fsum
        #pragma unroll
        for (int it = 0; it < 4; ++it) {
            int s = tid + it * THREADS;         // 0..1023
            int row = s >> 5, q = s & 31;
            int n = n0 + row;
            float4 v = make_float4(0.f, 0.f, 0.f, 0.f);
            if (n < N) v = Fg4[((size_t)n * MM + m) * 32 + q];
            st_split(smem, SF_HI, SF_LO, bswz(row, q), v);
            fsum[it].x += v.x; fsum[it].y += v.y;
            fsum[it].z += v.z; fsum[it].w += v.w;
        }
        __syncthreads();

        float acc[4][4];
        #pragma unroll
        for (int t = 0; t < 4; ++t)
            #pragma unroll
            for (int c = 0; c < 4; ++c) acc[t][c] = 0.f;

        #pragma unroll
        for (int kk = 0; kk < 8; ++kk) {
            uint32_t ah0, ah1, ah2, ah3, al0, al1, al2, al3;
            uint32_t aaddr_h = lmaddr(sb + SF_HI, a_row, 2 * kk + a_ch);
            uint32_t aaddr_l = lmaddr(sb + SF_LO, a_row, 2 * kk + a_ch);
            LDSM_X4(ah0, ah1, ah2, ah3, aaddr_h);
            LDSM_X4(al0, al1, al2, al3, aaddr_l);

            uint32_t bh[8], bl[8];
            #pragma unroll
            for (int p = 0; p < 2; ++p) {       // e-tile pairs: cols 32wc+16p..
                int brow = 32 * wc + 16 * p + b_rlo;
                uint32_t baddr_h = lmaddr(sb + SW_HI, brow, 2 * kk + b_ch);
                uint32_t baddr_l = lmaddr(sb + SW_LO, brow, 2 * kk + b_ch);
                LDSM_X4(bh[4*p+0], bh[4*p+1], bh[4*p+2], bh[4*p+3], baddr_h);
                LDSM_X4(bl[4*p+0], bl[4*p+1], bl[4*p+2], bl[4*p+3], baddr_l);
            }
            // t-th e-tile uses b regs {2t, 2t+1}
            #pragma unroll
            for (int t = 0; t < 4; ++t)
                HMMA(acc[t][0], acc[t][1], acc[t][2], acc[t][3],
                     ah0, ah1, ah2, ah3, bh[2*t], bh[2*t+1]);
            #pragma unroll
            for (int t = 0; t < 4; ++t)
                HMMA(acc[t][0], acc[t][1], acc[t][2], acc[t][3],
                     ah0, ah1, ah2, ah3, bl[2*t], bl[2*t+1]);
            #pragma unroll
            for (int t = 0; t < 4; ++t)
                HMMA(acc[t][0], acc[t][1], acc[t][2], acc[t][3],
                     al0, al1, al2, al3, bh[2*t], bh[2*t+1]);
        }

        // relu + store to sG.  d layout: c0,c1 -> row lane>>2, cols (lane&3)*2 +0,1
        //                                c2,c3 -> row+8
        {
            const int r0 = 16 * wr + (lane >> 2);
            const int cbase = 32 * wc + (lane & 3) * 2;
            #pragma unroll
            for (int t = 0; t < 4; ++t) {
                const int col = cbase + 8 * t;
                float2 lo = make_float2(fmaxf(acc[t][0], 0.f), fmaxf(acc[t][1], 0.f));
                float2 hi = make_float2(fmaxf(acc[t][2], 0.f), fmaxf(acc[t][3], 0.f));
                *reinterpret_cast<float2*>(sG + ((r0    ) * MM + m) * DD + col) = lo;
                *reinterpret_cast<float2*>(sG + ((r0 + 8) * MM + m) * DD + col) = hi;
            }
        }
    }
    __syncthreads();

    // spill fsum into the (dead) f-tile smem region (fp32, 16 KB)
    float4* sFs4 = reinterpret_cast<float4*>(smem + SF_HI);
    #pragma unroll
    for (int it = 0; it < 4; ++it) sFs4[tid + it * THREADS] = fsum[it];
    __syncthreads();

    // ------------- Phase 2: edges column-sum + output -------------------------
    const float4* sG4 = reinterpret_cast<const float4*>(sG);
    float4* out4 = reinterpret_cast<float4*>(out);

    #pragma unroll
    for (int ii = 0; ii < 4; ++ii) {
        const int i = warp * 4 + ii;
        const int n = n0 + i;

        float4 gm[MM];
        #pragma unroll
        for (int m = 0; m < MM; ++m)
            gm[m] = sG4[(i * MM + m) * 32 + lane];

        float sp[36];
        #pragma unroll
        for (int j = 0; j < MM; ++j)
            #pragma unroll
            for (int k = j + 1; k < MM; ++k) {
                float dx = gm[j].x - gm[k].x;
                float dy = gm[j].y - gm[k].y;
                float dz = gm[j].z - gm[k].z;
                float dw = gm[j].w - gm[k].w;
                float s = dx * dx;
                s = fmaf(dy, dy, s);
                s = fmaf(dz, dz, s);
                s = fmaf(dw, dw, s);
                sp[pidx(j, k)] = s;
            }

        float mysA = 1.f, mysB = 1.f;
        #pragma unroll
        for (int p = 0; p < 36; ++p) {
            float v = sp[p];
            v += __shfl_xor_sync(0xffffffffu, v, 16);
            v += __shfl_xor_sync(0xffffffffu, v, 8);
            v += __shfl_xor_sync(0xffffffffu, v, 4);
            v += __shfl_xor_sync(0xffffffffu, v, 2);
            v += __shfl_xor_sync(0xffffffffu, v, 1);
            if (p < 32) { if (lane == p)      mysA = v; }
            else        { if (lane == p - 32) mysB = v; }
        }

        float xA = (mysA > 0.f) ? mysA * __frsqrt_rn(mysA) : 0.f;
        float xB = (mysB > 0.f) ? mysB * __frsqrt_rn(mysB) : 0.f;
        float eA = 1.f - __fdividef(2.f, __expf(2.f * xA) + 1.f);
        float eB = 1.f - __fdividef(2.f, __expf(2.f * xB) + 1.f);

        float cs[MM];
        #pragma unroll
        for (int k = 0; k < MM; ++k) {
            float a = 0.f;
            #pragma unroll
            for (int j = 0; j < MM; ++j) {
                if (j == k) continue;
                const int p = (j < k) ? pidx(j, k) : pidx(k, j);
                float e = (p < 32) ? __shfl_sync(0xffffffffu, eA, p)
                                   : __shfl_sync(0xffffffffu, eB, p - 32);
                a += e;
            }
            cs[k] = a;
        }

        float4 fs = sFs4[i * 32 + lane];
        float ux = 0.f, uy = 0.f, uz = 0.f, uw = 0.f;
        #pragma unroll
        for (int k = 0; k < MM; ++k) {
            ux = fmaf(cs[k], gm[k].x, ux);
            uy = fmaf(cs[k], gm[k].y, uy);
            uz = fmaf(cs[k], gm[k].z, uz);
            uw = fmaf(cs[k], gm[k].w, uw);
        }
        if (n < N) {
            float4 o;
            o.x = 0.5f * (fs.x + ux);
            o.y = 0.5f * (fs.y + uy);
            o.z = 0.5f * (fs.z + uz);
            o.w = 0.5f * (fs.w + uw);
            out4[(size_t)n * 32 + lane] = o;
        }
    }
}

extern "C" void kernel_launch(void* const* d_in, const int* in_sizes, int n_in,
                              void* d_out, int out_size) {
    const float* F = (const float*)d_in[0];
    const float* W = (const float*)d_in[1];
    float* out = (float*)d_out;
    const int N = in_sizes[0] / (MM * DD);

    cudaFuncSetAttribute(inter_rm_mma,
                         cudaFuncAttributeMaxDynamicSharedMemorySize, SMEM_BYTES);
    const int grid = (N + NT - 1) / NT;
    inter_rm_mma<<<grid, THREADS, SMEM_BYTES>>>(F, W, out, N);
}

// round 5
// speedup vs baseline: 1.4270x; 1.0265x over previous
#include <cuda_runtime.h>
#include <cuda_bf16.h>
#include <cstdint>

#define MM 9
#define DD 128
#define NMAX 8192
#define NTILES (NMAX / 64)     // 128

// ---------------- global scratch (static, no dynamic alloc) ----------------
static __device__ __align__(128) __nv_bfloat16 Whi_g[MM * 128 * 128];
static __device__ __align__(128) __nv_bfloat16 Wlo_g[MM * 128 * 128];
static __device__ __align__(128) __nv_bfloat16 fhi_g[NTILES * MM * 64 * 128];
static __device__ __align__(128) __nv_bfloat16 flo_g[NTILES * MM * 64 * 128];
static __device__ __align__(128) float g_g[NMAX * MM * DD];
static __device__ __align__(128) float fsum_g[NMAX * DD];

// ---------------- helpers ---------------------------------------------------
// swizzled byte offset of (row, float4-slot q) in a [rows x 128] bf16 tile
__device__ __forceinline__ uint32_t bswz(int row, int q) {
    int c = q >> 1;
    int cs = (c & 8) | ((c & 7) ^ (row & 7));
    return (uint32_t)(row * 256 + cs * 16 + (q & 1) * 8);
}
__device__ __forceinline__ uint32_t lmaddr(uint32_t base, int row, int chunk) {
    int cs = (chunk & 8) | ((chunk & 7) ^ (row & 7));
    return base + (uint32_t)(row * 256 + cs * 16);
}
__device__ __forceinline__ uint32_t smem_u32(const void* p) {
    uint32_t a;
    asm("{ .reg .u64 t; cvta.to.shared.u64 t, %1; cvt.u32.u64 %0, t; }" : "=r"(a) : "l"(p));
    return a;
}
#define LDSM_X4(r0, r1, r2, r3, a) \
    asm volatile("ldmatrix.sync.aligned.m8n8.x4.shared.b16 {%0,%1,%2,%3}, [%4];" \
                 : "=r"(r0), "=r"(r1), "=r"(r2), "=r"(r3) : "r"(a))
#define HMMA(d0, d1, d2, d3, a0, a1, a2, a3, b0, b1) \
    asm volatile("mma.sync.aligned.m16n8k16.row.col.f32.bf16.bf16.f32 " \
                 "{%0,%1,%2,%3}, {%4,%5,%6,%7}, {%8,%9}, {%0,%1,%2,%3};" \
                 : "+f"(d0), "+f"(d1), "+f"(d2), "+f"(d3) \
                 : "r"(a0), "r"(a1), "r"(a2), "r"(a3), "r"(b0), "r"(b1))
#define CP16(dst, src) \
    asm volatile("cp.async.cg.shared.global [%0], [%1], 16;" :: "r"(dst), "l"(src))
#define CP_COMMIT() asm volatile("cp.async.commit_group;")
#define CP_WAIT0()  asm volatile("cp.async.wait_group 0;" ::: "memory")

// split one float4 into hi/lo bf16 quads, store 8B to each destination
__device__ __forceinline__ void st_split_g(char* hi, char* lo, uint32_t a, float4 v) {
    __nv_bfloat16 hx = __float2bfloat16(v.x), hy = __float2bfloat16(v.y);
    __nv_bfloat16 hz = __float2bfloat16(v.z), hw = __float2bfloat16(v.w);
    __nv_bfloat16 lx = __float2bfloat16(v.x - __bfloat162float(hx));
    __nv_bfloat16 ly = __float2bfloat16(v.y - __bfloat162float(hy));
    __nv_bfloat16 lz = __float2bfloat16(v.z - __bfloat162float(hz));
    __nv_bfloat16 lw = __float2bfloat16(v.w - __bfloat162float(hw));
    uint2 h = make_uint2((uint32_t)__bfloat16_as_ushort(hx) | ((uint32_t)__bfloat16_as_ushort(hy) << 16),
                         (uint32_t)__bfloat16_as_ushort(hz) | ((uint32_t)__bfloat16_as_ushort(hw) << 16));
    uint2 l = make_uint2((uint32_t)__bfloat16_as_ushort(lx) | ((uint32_t)__bfloat16_as_ushort(ly) << 16),
                         (uint32_t)__bfloat16_as_ushort(lz) | ((uint32_t)__bfloat16_as_ushort(lw) << 16));
    *reinterpret_cast<uint2*>(hi + a) = h;
    *reinterpret_cast<uint2*>(lo + a) = l;
}

// ---------------- K0a: W -> split bf16, pre-swizzled ------------------------
__global__ void __launch_bounds__(256)
k0a_prepW(const float* __restrict__ Wg)
{
    const int m = blockIdx.x;
    const int tid = threadIdx.x;
    const float4* Wg4 = reinterpret_cast<const float4*>(Wg);
    char* hi = reinterpret_cast<char*>(Whi_g) + (size_t)m * 32768;
    char* lo = reinterpret_cast<char*>(Wlo_g) + (size_t)m * 32768;
    #pragma unroll
    for (int it = 0; it < 16; ++it) {
        int s = tid + it * 256;            // 0..4095
        int row = s >> 5, q = s & 31;
        st_split_g(hi, lo, bswz(row, q), Wg4[(size_t)m * 4096 + s]);
    }
}

// ---------------- K0b: f -> split bf16 tiles + fsum -------------------------
__global__ void __launch_bounds__(512)
k0b_prepF(const float* __restrict__ F, int N)
{
    const int ntile = blockIdx.x;          // 64 examples per tile
    const int tid = threadIdx.x;
    const int n0 = ntile * 64;
    const float4* Fg4 = reinterpret_cast<const float4*>(F);

    float4 fs[4];
    #pragma unroll
    for (int r = 0; r < 4; ++r) fs[r] = make_float4(0.f, 0.f, 0.f, 0.f);

    for (int m = 0; m < MM; ++m) {
        char* hi = reinterpret_cast<char*>(fhi_g) + ((size_t)ntile * MM + m) * 16384;
        char* lo = reinterpret_cast<char*>(flo_g) + ((size_t)ntile * MM + m) * 16384;
        #pragma unroll
        for (int it = 0; it < 4; ++it) {
            int s = tid + it * 512;        // 0..2047
            int row = s >> 5, q = s & 31;
            int n = n0 + row;
            float4 v = make_float4(0.f, 0.f, 0.f, 0.f);
            if (n < N) v = Fg4[((size_t)n * MM + m) * 32 + q];
            st_split_g(hi, lo, bswz(row, q), v);
            fs[it].x += v.x; fs[it].y += v.y; fs[it].z += v.z; fs[it].w += v.w;
        }
    }
    float4* fd = reinterpret_cast<float4*>(fsum_g);
    #pragma unroll
    for (int it = 0; it < 4; ++it) {
        int s = tid + it * 512;
        int row = s >> 5, q = s & 31;
        int n = n0 + row;
        if (n < N) fd[(size_t)n * 32 + q] = fs[it];
    }
}

// ---------------- K1: g = relu(f @ W_m^T), split-bf16 HMMA -------------------
// grid (NTILES, 9), 256 threads, smem: fhi 16K | flo 16K | Whi 32K | Wlo 32K
#define SM_FHI 0
#define SM_FLO 16384
#define SM_WHI 32768
#define SM_WLO 65536
#define K1_SMEM 98304

__global__ void __launch_bounds__(256, 2)
k1_gemm(int N)
{
    extern __shared__ char smem[];
    const uint32_t sb = smem_u32(smem);
    const int tid  = threadIdx.x;
    const int lane = tid & 31;
    const int warp = tid >> 5;          // 0..7
    const int rg   = warp & 3;          // row group: rows [16rg, 16rg+16)
    const int cg   = warp >> 2;         // col group: cols [64cg, 64cg+64)
    const int ntile = blockIdx.x;
    const int m     = blockIdx.y;
    const int n0    = ntile * 64;

    // async loads (swizzle baked into gmem layout)
    {
        const char* fh = reinterpret_cast<const char*>(fhi_g) + ((size_t)ntile * MM + m) * 16384;
        const char* fl = reinterpret_cast<const char*>(flo_g) + ((size_t)ntile * MM + m) * 16384;
        const char* wh = reinterpret_cast<const char*>(Whi_g) + (size_t)m * 32768;
        const char* wl = reinterpret_cast<const char*>(Wlo_g) + (size_t)m * 32768;
        #pragma unroll
        for (int i = 0; i < 4; ++i) {
            uint32_t o = (uint32_t)(tid + i * 256) * 16;
            CP16(sb + SM_FHI + o, fh + o);
            CP16(sb + SM_FLO + o, fl + o);
        }
        #pragma unroll
        for (int i = 0; i < 8; ++i) {
            uint32_t o = (uint32_t)(tid + i * 256) * 16;
            CP16(sb + SM_WHI + o, wh + o);
            CP16(sb + SM_WLO + o, wl + o);
        }
        CP_COMMIT();
        CP_WAIT0();
        __syncthreads();
    }

    const int a_row = 16 * rg + (lane & 15);
    const int a_ch  = lane >> 4;
    const int b_rlo = (lane & 7) + ((lane >> 4) << 3);
    const int b_ch  = (lane >> 3) & 1;

    float acc[8][4];
    #pragma unroll
    for (int t = 0; t < 8; ++t)
        #pragma unroll
        for (int c = 0; c < 4; ++c) acc[t][c] = 0.f;

    #pragma unroll
    for (int kk = 0; kk < 8; ++kk) {
        uint32_t ah0, ah1, ah2, ah3, al0, al1, al2, al3;
        LDSM_X4(ah0, ah1, ah2, ah3, lmaddr(sb + SM_FHI, a_row, 2 * kk + a_ch));
        LDSM_X4(al0, al1, al2, al3, lmaddr(sb + SM_FLO, a_row, 2 * kk + a_ch));

        uint32_t bh[16], bl[16];
        #pragma unroll
        for (int p = 0; p < 4; ++p) {
            int brow = 64 * cg + 16 * p + b_rlo;
            LDSM_X4(bh[4*p+0], bh[4*p+1], bh[4*p+2], bh[4*p+3],
                    lmaddr(sb + SM_WHI, brow, 2 * kk + b_ch));
            LDSM_X4(bl[4*p+0], bl[4*p+1], bl[4*p+2], bl[4*p+3],
                    lmaddr(sb + SM_WLO, brow, 2 * kk + b_ch));
        }
        #pragma unroll
        for (int t = 0; t < 8; ++t)
            HMMA(acc[t][0], acc[t][1], acc[t][2], acc[t][3],
                 ah0, ah1, ah2, ah3, bh[2*t], bh[2*t+1]);
        #pragma unroll
        for (int t = 0; t < 8; ++t)
            HMMA(acc[t][0], acc[t][1], acc[t][2], acc[t][3],
                 ah0, ah1, ah2, ah3, bl[2*t], bl[2*t+1]);
        #pragma unroll
        for (int t = 0; t < 8; ++t)
            HMMA(acc[t][0], acc[t][1], acc[t][2], acc[t][3],
                 al0, al1, al2, al3, bh[2*t], bh[2*t+1]);
    }

    // relu + store g[n][m][col]
    const int r0 = n0 + 16 * rg + (lane >> 2);
    const int cb = 64 * cg + (lane & 3) * 2;
    #pragma unroll
    for (int t = 0; t < 8; ++t) {
        const int col = cb + 8 * t;
        if (r0 < N) {
            float2 v = make_float2(fmaxf(acc[t][0], 0.f), fmaxf(acc[t][1], 0.f));
            *reinterpret_cast<float2*>(g_g + ((size_t)r0 * MM + m) * DD + col) = v;
        }
        if (r0 + 8 < N) {
            float2 v = make_float2(fmaxf(acc[t][2], 0.f), fmaxf(acc[t][3], 0.f));
            *reinterpret_cast<float2*>(g_g + ((size_t)(r0 + 8) * MM + m) * DD + col) = v;
        }
    }
}

// ---------------- K2: edges column-sum + output ------------------------------
__device__ __forceinline__ constexpr int pidx(int j, int k) {
    return j * 8 - j * (j - 1) / 2 + (k - j - 1);
}

__global__ void __launch_bounds__(256, 2)
k2_phase2(float* __restrict__ out, int N)
{
    const int tid  = threadIdx.x;
    const int lane = tid & 31;
    const int warp = tid >> 5;
    const int n0   = blockIdx.x * 32;
    const float4* g4 = reinterpret_cast<const float4*>(g_g);
    const float4* fs4 = reinterpret_cast<const float4*>(fsum_g);
    float4* out4 = reinterpret_cast<float4*>(out);

    #pragma unroll
    for (int ii = 0; ii < 4; ++ii) {
        const int n = n0 + warp * 4 + ii;
        if (n >= N) continue;

        float4 gm[MM];
        #pragma unroll
        for (int m = 0; m < MM; ++m)
            gm[m] = g4[((size_t)n * MM + m) * 32 + lane];

        float sp[36];
        #pragma unroll
        for (int j = 0; j < MM; ++j)
            #pragma unroll
            for (int k = j + 1; k < MM; ++k) {
                float dx = gm[j].x - gm[k].x;
                float dy = gm[j].y - gm[k].y;
                float dz = gm[j].z - gm[k].z;
                float dw = gm[j].w - gm[k].w;
                float s = dx * dx;
                s = fmaf(dy, dy, s);
                s = fmaf(dz, dz, s);
                s = fmaf(dw, dw, s);
                sp[pidx(j, k)] = s;
            }

        float mysA = 1.f, mysB = 1.f;
        #pragma unroll
        for (int p = 0; p < 36; ++p) {
            float v = sp[p];
            v += __shfl_xor_sync(0xffffffffu, v, 16);
            v += __shfl_xor_sync(0xffffffffu, v, 8);
            v += __shfl_xor_sync(0xffffffffu, v, 4);
            v += __shfl_xor_sync(0xffffffffu, v, 2);
            v += __shfl_xor_sync(0xffffffffu, v, 1);
            if (p < 32) { if (lane == p)      mysA = v; }
            else        { if (lane == p - 32) mysB = v; }
        }

        float xA = (mysA > 0.f) ? mysA * __frsqrt_rn(mysA) : 0.f;
        float xB = (mysB > 0.f) ? mysB * __frsqrt_rn(mysB) : 0.f;
        float eA = 1.f - __fdividef(2.f, __expf(2.f * xA) + 1.f);
        float eB = 1.f - __fdividef(2.f, __expf(2.f * xB) + 1.f);

        float cs[MM];
        #pragma unroll
        for (int k = 0; k < MM; ++k) {
            float a = 0.f;
            #pragma unroll
            for (int j = 0; j < MM; ++j) {
                if (j == k) continue;
                const int p = (j < k) ? pidx(j, k) : pidx(k, j);
                float e = (p < 32) ? __shfl_sync(0xffffffffu, eA, p)
                                   : __shfl_sync(0xffffffffu, eB, p - 32);
                a += e;
            }
            cs[k] = a;
        }

        float4 fs = fs4[(size_t)n * 32 + lane];
        float ux = 0.f, uy = 0.f, uz = 0.f, uw = 0.f;
        #pragma unroll
        for (int k = 0; k < MM; ++k) {
            ux = fmaf(cs[k], gm[k].x, ux);
            uy = fmaf(cs[k], gm[k].y, uy);
            uz = fmaf(cs[k], gm[k].z, uz);
            uw = fmaf(cs[k], gm[k].w, uw);
        }
        float4 o;
        o.x = 0.5f * (fs.x + ux);
        o.y = 0.5f * (fs.y + uy);
        o.z = 0.5f * (fs.z + uz);
        o.w = 0.5f * (fs.w + uw);
        out4[(size_t)n * 32 + lane] = o;
    }
}

// ----------------------------------------------------------------------------
extern "C" void kernel_launch(void* const* d_in, const int* in_sizes, int n_in,
                              void* d_out, int out_size) {
    const float* F = (const float*)d_in[0];   // [N,9,128] fp32
    const float* W = (const float*)d_in[1];   // [9,128,128] fp32
    float* out = (float*)d_out;               // [N,128] fp32
    const int N = in_sizes[0] / (MM * DD);

    cudaFuncSetAttribute(k1_gemm, cudaFuncAttributeMaxDynamicSharedMemorySize, K1_SMEM);

    const int ntiles = (N + 63) / 64;
    k0a_prepW<<<MM, 256>>>(W);
    k0b_prepF<<<ntiles, 512>>>(F, N);
    dim3 g1(ntiles, MM);
    k1_gemm<<<g1, 256, K1_SMEM>>>(N);
    k2_phase2<<<(N + 31) / 32, 256>>>(out, N);
}

// round 6
// speedup vs baseline: 1.9562x; 1.3708x over previous
#include <cuda_runtime.h>
#include <cuda_bf16.h>
#include <cstdint>

#define MM 9
#define DD 128
#define NMAX 8192

// ---------------- global scratch (static, no dynamic alloc) ----------------
static __device__ __align__(128) __nv_bfloat16 Whi_g[MM * 128 * 128];
static __device__ __align__(128) __nv_bfloat16 Wlo_g[MM * 128 * 128];
static __device__ __align__(128) float g_g[NMAX * MM * DD];

// ---------------- helpers ---------------------------------------------------
// swizzled byte offset of (row, float4-slot q) in a [rows x 128] bf16 tile
__device__ __forceinline__ uint32_t bswz(int row, int q) {
    int c = q >> 1;
    int cs = (c & 8) | ((c & 7) ^ (row & 7));
    return (uint32_t)(row * 256 + cs * 16 + (q & 1) * 8);
}
__device__ __forceinline__ uint32_t lmaddr(uint32_t base, int row, int chunk) {
    int cs = (chunk & 8) | ((chunk & 7) ^ (row & 7));
    return base + (uint32_t)(row * 256 + cs * 16);
}
__device__ __forceinline__ uint32_t smem_u32(const void* p) {
    uint32_t a;
    asm("{ .reg .u64 t; cvta.to.shared.u64 t, %1; cvt.u32.u64 %0, t; }" : "=r"(a) : "l"(p));
    return a;
}
#define LDSM_X4(r0, r1, r2, r3, a) \
    asm volatile("ldmatrix.sync.aligned.m8n8.x4.shared.b16 {%0,%1,%2,%3}, [%4];" \
                 : "=r"(r0), "=r"(r1), "=r"(r2), "=r"(r3) : "r"(a))
#define HMMA(d0, d1, d2, d3, a0, a1, a2, a3, b0, b1) \
    asm volatile("mma.sync.aligned.m16n8k16.row.col.f32.bf16.bf16.f32 " \
                 "{%0,%1,%2,%3}, {%4,%5,%6,%7}, {%8,%9}, {%0,%1,%2,%3};" \
                 : "+f"(d0), "+f"(d1), "+f"(d2), "+f"(d3) \
                 : "r"(a0), "r"(a1), "r"(a2), "r"(a3), "r"(b0), "r"(b1))
#define CP16(dst, src) \
    asm volatile("cp.async.cg.shared.global [%0], [%1], 16;" :: "r"(dst), "l"(src))
#define CP_COMMIT() asm volatile("cp.async.commit_group;")
#define CP_WAIT0()  asm volatile("cp.async.wait_group 0;" ::: "memory")

// split one float4 into hi/lo bf16 quads, store 8B to each destination
__device__ __forceinline__ void st_split_g(char* hi, char* lo, uint32_t a, float4 v) {
    __nv_bfloat16 hx = __float2bfloat16(v.x), hy = __float2bfloat16(v.y);
    __nv_bfloat16 hz = __float2bfloat16(v.z), hw = __float2bfloat16(v.w);
    __nv_bfloat16 lx = __float2bfloat16(v.x - __bfloat162float(hx));
    __nv_bfloat16 ly = __float2bfloat16(v.y - __bfloat162float(hy));
    __nv_bfloat16 lz = __float2bfloat16(v.z - __bfloat162float(hz));
    __nv_bfloat16 lw = __float2bfloat16(v.w - __bfloat162float(hw));
    uint2 h = make_uint2((uint32_t)__bfloat16_as_ushort(hx) | ((uint32_t)__bfloat16_as_ushort(hy) << 16),
                         (uint32_t)__bfloat16_as_ushort(hz) | ((uint32_t)__bfloat16_as_ushort(hw) << 16));
    uint2 l = make_uint2((uint32_t)__bfloat16_as_ushort(lx) | ((uint32_t)__bfloat16_as_ushort(ly) << 16),
                         (uint32_t)__bfloat16_as_ushort(lz) | ((uint32_t)__bfloat16_as_ushort(lw) << 16));
    *reinterpret_cast<uint2*>(hi + a) = h;
    *reinterpret_cast<uint2*>(lo + a) = l;
}

// ---------------- K0: W -> split bf16, pre-swizzled -------------------------
__global__ void __launch_bounds__(256)
k0_prepW(const float* __restrict__ Wg)
{
    const int m = blockIdx.x;
    const int tid = threadIdx.x;
    const float4* Wg4 = reinterpret_cast<const float4*>(Wg);
    char* hi = reinterpret_cast<char*>(Whi_g) + (size_t)m * 32768;
    char* lo = reinterpret_cast<char*>(Wlo_g) + (size_t)m * 32768;
    #pragma unroll
    for (int it = 0; it < 16; ++it) {
        int s = tid + it * 256;            // 0..4095
        int row = s >> 5, q = s & 31;
        st_split_g(hi, lo, bswz(row, q), Wg4[(size_t)m * 4096 + s]);
    }
}

// ---------------- K1: g = relu(f @ W_m^T), split-bf16 HMMA -------------------
// grid (ntiles, 9), 256 threads; smem: fhi 16K | flo 16K | Whi 32K | Wlo 32K
#define SM_FHI 0
#define SM_FLO 16384
#define SM_WHI 32768
#define SM_WLO 65536
#define K1_SMEM 98304

__global__ void __launch_bounds__(256, 2)
k1_gemm(const float* __restrict__ F, int N)
{
    extern __shared__ char smem[];
    const uint32_t sb = smem_u32(smem);
    const int tid  = threadIdx.x;
    const int lane = tid & 31;
    const int warp = tid >> 5;          // 0..7
    const int rg   = warp & 3;          // row group: rows [16rg, 16rg+16)
    const int cg   = warp >> 2;         // col group: cols [64cg, 64cg+64)
    const int ntile = blockIdx.x;
    const int m     = blockIdx.y;
    const int n0    = ntile * 64;

    // 1) kick off W split-tile loads (L2-resident after first wave)
    {
        const char* wh = reinterpret_cast<const char*>(Whi_g) + (size_t)m * 32768;
        const char* wl = reinterpret_cast<const char*>(Wlo_g) + (size_t)m * 32768;
        #pragma unroll
        for (int i = 0; i < 8; ++i) {
            uint32_t o = (uint32_t)(tid + i * 256) * 16;
            CP16(sb + SM_WHI + o, wh + o);
            CP16(sb + SM_WLO + o, wl + o);
        }
        CP_COMMIT();
    }
    // 2) convert f tile fp32 -> split bf16 in smem (overlaps W DMA)
    {
        const float4* Fg4 = reinterpret_cast<const float4*>(F);
        #pragma unroll
        for (int it = 0; it < 8; ++it) {
            int s = tid + it * 256;        // 0..2047
            int row = s >> 5, q = s & 31;
            int n = n0 + row;
            float4 v = make_float4(0.f, 0.f, 0.f, 0.f);
            if (n < N) v = Fg4[((size_t)n * MM + m) * 32 + q];
            st_split_g(smem + SM_FHI, smem + SM_FLO, bswz(row, q), v);
        }
    }
    CP_WAIT0();
    __syncthreads();

    const int a_row = 16 * rg + (lane & 15);
    const int a_ch  = lane >> 4;
    const int b_rlo = (lane & 7) + ((lane >> 4) << 3);
    const int b_ch  = (lane >> 3) & 1;

    float acc[8][4];
    #pragma unroll
    for (int t = 0; t < 8; ++t)
        #pragma unroll
        for (int c = 0; c < 4; ++c) acc[t][c] = 0.f;

    #pragma unroll
    for (int kk = 0; kk < 8; ++kk) {
        uint32_t ah0, ah1, ah2, ah3, al0, al1, al2, al3;
        LDSM_X4(ah0, ah1, ah2, ah3, lmaddr(sb + SM_FHI, a_row, 2 * kk + a_ch));
        LDSM_X4(al0, al1, al2, al3, lmaddr(sb + SM_FLO, a_row, 2 * kk + a_ch));

        #pragma unroll
        for (int p = 0; p < 4; ++p) {      // 16 output cols per step
            const int brow = 64 * cg + 16 * p + b_rlo;
            uint32_t b0, b1, b2, b3, c0, c1, c2, c3;
            LDSM_X4(b0, b1, b2, b3, lmaddr(sb + SM_WHI, brow, 2 * kk + b_ch));
            LDSM_X4(c0, c1, c2, c3, lmaddr(sb + SM_WLO, brow, 2 * kk + b_ch));
            const int t0 = 2 * p, t1 = 2 * p + 1;
            HMMA(acc[t0][0], acc[t0][1], acc[t0][2], acc[t0][3],
                 ah0, ah1, ah2, ah3, b0, b1);
            HMMA(acc[t1][0], acc[t1][1], acc[t1][2], acc[t1][3],
                 ah0, ah1, ah2, ah3, b2, b3);
            HMMA(acc[t0][0], acc[t0][1], acc[t0][2], acc[t0][3],
                 ah0, ah1, ah2, ah3, c0, c1);
            HMMA(acc[t1][0], acc[t1][1], acc[t1][2], acc[t1][3],
                 ah0, ah1, ah2, ah3, c2, c3);
            HMMA(acc[t0][0], acc[t0][1], acc[t0][2], acc[t0][3],
                 al0, al1, al2, al3, b0, b1);
            HMMA(acc[t1][0], acc[t1][1], acc[t1][2], acc[t1][3],
                 al0, al1, al2, al3, b2, b3);
        }
    }

    // relu + store g[n][m][col]
    const int r0 = n0 + 16 * rg + (lane >> 2);
    const int cb = 64 * cg + (lane & 3) * 2;
    #pragma unroll
    for (int t = 0; t < 8; ++t) {
        const int col = cb + 8 * t;
        if (r0 < N) {
            float2 v = make_float2(fmaxf(acc[t][0], 0.f), fmaxf(acc[t][1], 0.f));
            *reinterpret_cast<float2*>(g_g + ((size_t)r0 * MM + m) * DD + col) = v;
        }
        if (r0 + 8 < N) {
            float2 v = make_float2(fmaxf(acc[t][2], 0.f), fmaxf(acc[t][3], 0.f));
            *reinterpret_cast<float2*>(g_g + ((size_t)(r0 + 8) * MM + m) * DD + col) = v;
        }
    }
}

// ---------------- K2: edges column-sum + fsum + output -----------------------
__device__ __forceinline__ constexpr int pidx(int j, int k) {
    return j * 8 - j * (j - 1) / 2 + (k - j - 1);
}

__global__ void __launch_bounds__(256)
k2_phase2(const float* __restrict__ F, float* __restrict__ out, int N)
{
    const int tid  = threadIdx.x;
    const int lane = tid & 31;
    const int warp = tid >> 5;
    const int n0   = blockIdx.x * 32;
    const float4* g4  = reinterpret_cast<const float4*>(g_g);
    const float4* Fg4 = reinterpret_cast<const float4*>(F);
    float4* out4 = reinterpret_cast<float4*>(out);

    #pragma unroll
    for (int ii = 0; ii < 4; ++ii) {
        const int n = n0 + warp * 4 + ii;
        if (n >= N) continue;

        float4 gm[MM];
        #pragma unroll
        for (int m = 0; m < MM; ++m)
            gm[m] = g4[((size_t)n * MM + m) * 32 + lane];

        // fsum over m (exact fp32), loads overlap the shuffle chains below
        float4 fs = Fg4[((size_t)n * MM) * 32 + lane];
        #pragma unroll
        for (int m = 1; m < MM; ++m) {
            float4 v = Fg4[((size_t)n * MM + m) * 32 + lane];
            fs.x += v.x; fs.y += v.y; fs.z += v.z; fs.w += v.w;
        }

        // pairwise distances with inline butterfly (1 live reg per pair)
        float mysA = 1.f, mysB = 1.f;
        #pragma unroll
        for (int j = 0; j < MM; ++j) {
            #pragma unroll
            for (int k = j + 1; k < MM; ++k) {
                const int p = pidx(j, k);
                float dx = gm[j].x - gm[k].x;
                float dy = gm[j].y - gm[k].y;
                float dz = gm[j].z - gm[k].z;
                float dw = gm[j].w - gm[k].w;
                float s = dx * dx;
                s = fmaf(dy, dy, s);
                s = fmaf(dz, dz, s);
                s = fmaf(dw, dw, s);
                s += __shfl_xor_sync(0xffffffffu, s, 16);
                s += __shfl_xor_sync(0xffffffffu, s, 8);
                s += __shfl_xor_sync(0xffffffffu, s, 4);
                s += __shfl_xor_sync(0xffffffffu, s, 2);
                s += __shfl_xor_sync(0xffffffffu, s, 1);
                if (p < 32) { if (lane == p)      mysA = s; }
                else        { if (lane == p - 32) mysB = s; }
            }
        }

        float xA = (mysA > 0.f) ? mysA * __frsqrt_rn(mysA) : 0.f;
        float xB = (mysB > 0.f) ? mysB * __frsqrt_rn(mysB) : 0.f;
        float eA = 1.f - __fdividef(2.f, __expf(2.f * xA) + 1.f);
        float eB = 1.f - __fdividef(2.f, __expf(2.f * xB) + 1.f);

        float cs[MM];
        #pragma unroll
        for (int k = 0; k < MM; ++k) {
            float a = 0.f;
            #pragma unroll
            for (int j = 0; j < MM; ++j) {
                if (j == k) continue;
                const int p = (j < k) ? pidx(j, k) : pidx(k, j);
                float e = (p < 32) ? __shfl_sync(0xffffffffu, eA, p)
                                   : __shfl_sync(0xffffffffu, eB, p - 32);
                a += e;
            }
            cs[k] = a;
        }

        float ux = 0.f, uy = 0.f, uz = 0.f, uw = 0.f;
        #pragma unroll
        for (int k = 0; k < MM; ++k) {
            ux = fmaf(cs[k], gm[k].x, ux);
            uy = fmaf(cs[k], gm[k].y, uy);
            uz = fmaf(cs[k], gm[k].z, uz);
            uw = fmaf(cs[k], gm[k].w, uw);
        }
        float4 o;
        o.x = 0.5f * (fs.x + ux);
        o.y = 0.5f * (fs.y + uy);
        o.z = 0.5f * (fs.z + uz);
        o.w = 0.5f * (fs.w + uw);
        out4[(size_t)n * 32 + lane] = o;
    }
}

// ----------------------------------------------------------------------------
extern "C" void kernel_launch(void* const* d_in, const int* in_sizes, int n_in,
                              void* d_out, int out_size) {
    const float* F = (const float*)d_in[0];   // [N,9,128] fp32
    const float* W = (const float*)d_in[1];   // [9,128,128] fp32
    float* out = (float*)d_out;               // [N,128] fp32
    const int N = in_sizes[0] / (MM * DD);

    cudaFuncSetAttribute(k1_gemm, cudaFuncAttributeMaxDynamicSharedMemorySize, K1_SMEM);

    const int ntiles = (N + 63) / 64;
    k0_prepW<<<MM, 256>>>(W);
    dim3 g1(ntiles, MM);
    k1_gemm<<<g1, 256, K1_SMEM>>>(F, N);
    k2_phase2<<<(N + 31) / 32, 256>>>(F, out, N);
}